// round 7
// baseline (speedup 1.0000x reference)
#include <cuda_runtime.h>
#include <cstdint>
#include <cstddef>

// Jordan GRU, B=128, T=2048, I=128, H=256, O=64.
// 16 clusters x 8 CTAs. CTA = 8 batch rows x 32 hidden units, 512 threads.
// Thread = (b-pair, unit, K-quarter), 2 batch rows per thread.
// Data exchanged through L2 (STG/LDG); signaling via cluster mbarriers.

#define TSTEPS 2048
#define INSZ 128
#define HID 256
#define OUTSZ 64
#define GIN 192
#define NBLK 128
#define NTHR 512
#define ROWS 8
#define UNITS 32

#define HS 260
#define XS 132
#define YS 68
#define WHS 260
#define WIS 196
#define FCS 264
#define HSTG 36

// float offsets in dynamic smem
#define OFF_MB   0
#define OFF_H    16
#define OFF_X    (OFF_H + ROWS * HS)         // 2096
#define OFF_Y    (OFF_X + ROWS * XS)         // 3152
#define OFF_P    (OFF_Y + ROWS * YS)         // 3696  (3*256 float4)
#define OFF_YS   (OFF_P + 3 * 256 * 4)       // 6768
#define OFF_HST  (OFF_YS + 64)               // 6832
#define OFF_WHH  (OFF_HST + ROWS * HSTG)     // 7120
#define OFF_WIH  (OFF_WHH + 96 * WHS)        // 32080
#define OFF_FC   (OFF_WIH + 96 * WIS)        // 50896
#define OFF_BIH  (OFF_FC + 8 * FCS)          // 53008
#define OFF_BHH  (OFF_BIH + 96)
#define OFF_FCB  (OFF_BHH + 96)
#define SMEM_FLOATS (OFF_FCB + 16)           // 53224 -> 212,896 B

typedef unsigned long long ull;

__device__ float g_h[2][128 * HID];
__device__ float g_y[2][128 * OUTSZ];

__device__ __forceinline__ ull ffma2(ull a, ull b, ull c) {
    ull d; asm("fma.rn.f32x2 %0, %1, %2, %3;" : "=l"(d) : "l"(a), "l"(b), "l"(c));
    return d;
}
__device__ __forceinline__ float sumf2(ull v) {
    float a, b; asm("mov.b64 {%0, %1}, %2;" : "=f"(a), "=f"(b) : "l"(v));
    return a + b;
}
__device__ __forceinline__ uint32_t smem_u32(const void* p) {
    uint32_t a;
    asm("{ .reg .u64 t; cvta.to.shared.u64 t, %1; cvt.u32.u64 %0, t; }"
        : "=r"(a) : "l"(p));
    return a;
}
__device__ __forceinline__ uint32_t mapa32(uint32_t a, uint32_t rank) {
    uint32_t d; asm("mapa.shared::cluster.u32 %0, %1, %2;" : "=r"(d) : "r"(a), "r"(rank));
    return d;
}
__device__ __forceinline__ void mbar_init(uint32_t mb, uint32_t cnt) {
    asm volatile("mbarrier.init.shared.b64 [%0], %1;" :: "r"(mb), "r"(cnt) : "memory");
}
__device__ __forceinline__ void mbar_arrive_remote(uint32_t raddr) {
    asm volatile("mbarrier.arrive.release.cluster.shared::cluster.b64 _, [%0];"
                 :: "r"(raddr) : "memory");
}
__device__ __forceinline__ void wait_parity(uint32_t mb, uint32_t ph) {
    uint32_t done;
    asm volatile(
        "{\n\t.reg .pred p;\n\t"
        "mbarrier.try_wait.parity.acquire.cluster.shared::cta.b64 p, [%1], %2, 0x989680;\n\t"
        "selp.b32 %0, 1, 0, p;\n\t}"
        : "=r"(done) : "r"(mb), "r"(ph) : "memory");
    while (!done) {
        asm volatile(
            "{\n\t.reg .pred p;\n\t"
            "mbarrier.try_wait.parity.acquire.cluster.shared::cta.b64 p, [%1], %2, 0x989680;\n\t"
            "selp.b32 %0, 1, 0, p;\n\t}"
            : "=r"(done) : "r"(mb), "r"(ph) : "memory");
    }
}
__device__ __forceinline__ void barn(int id, int cnt) {
    asm volatile("bar.sync %0, %1;" :: "r"(id), "r"(cnt) : "memory");
}
__device__ __forceinline__ void cluster_sync_all() {
    asm volatile("barrier.cluster.arrive.aligned;" ::: "memory");
    asm volatile("barrier.cluster.wait.aligned;" ::: "memory");
}

__global__ void __launch_bounds__(NTHR, 1) __cluster_dims__(8, 1, 1)
jordan_kernel(
    const float* __restrict__ x,      // [B, T, I]
    const float* __restrict__ w_ih,   // [3H, GIN]
    const float* __restrict__ w_hh,   // [3H, H]
    const float* __restrict__ b_ih,   // [3H]
    const float* __restrict__ b_hh,   // [3H]
    const float* __restrict__ fc_w,   // [O, H]
    const float* __restrict__ fc_b,   // [O]
    float* __restrict__ out)          // [B, O]
{
    extern __shared__ float sm[];
    const uint32_t sbase = smem_u32(sm);

    float*  h_s    = sm + OFF_H;
    float*  x_s    = sm + OFF_X;
    float*  y_s    = sm + OFF_Y;
    float4* p_s    = reinterpret_cast<float4*>(sm + OFF_P);
    float*  ysum_s = sm + OFF_YS;
    float*  hstg_s = sm + OFF_HST;
    float*  whh_s  = sm + OFF_WHH;
    float*  wih_s  = sm + OFF_WIH;
    float*  fc_s   = sm + OFF_FC;
    float*  bih_s  = sm + OFF_BIH;
    float*  bhh_s  = sm + OFF_BHH;
    float*  fcb_s  = sm + OFF_FCB;

    const int tid    = threadIdx.x;
    const int q      = tid >> 7;         // K-quarter 0..3
    const int wg     = tid & 127;
    const int unit   = wg >> 2;          // 0..31
    const int b      = wg & 3;           // rows b and b+4

    const int blk   = blockIdx.x;
    const int slice = blk & 7;
    const int b0    = (blk >> 3) * ROWS;

    // ---- weights / biases / state init ----
    for (int i = tid; i < 96 * HID; i += NTHR) {
        int row = i >> 8, k = i & 255;
        whh_s[row * WHS + k] =
            w_hh[((row >> 5) * HID + slice * UNITS + (row & 31)) * HID + k];
    }
    for (int i = tid; i < 96 * GIN; i += NTHR) {
        int row = i / GIN, k = i - row * GIN;
        wih_s[row * WIS + k] =
            w_ih[((row >> 5) * HID + slice * UNITS + (row & 31)) * GIN + k];
    }
    for (int i = tid; i < 8 * HID; i += NTHR) {
        int r = i >> 8, k = i & 255;
        fc_s[r * FCS + k] = fc_w[(slice * 8 + r) * HID + k];
    }
    if (tid < 96) {
        int grow = (tid >> 5) * HID + slice * UNITS + (tid & 31);
        bih_s[tid] = b_ih[grow];
        bhh_s[tid] = b_hh[grow];
    }
    if (tid < 8) fcb_s[tid] = fc_b[slice * 8 + tid];
    for (int i = tid; i < ROWS * HS; i += NTHR) h_s[i] = 0.0f;
    for (int i = tid; i < ROWS * YS; i += NTHR) y_s[i] = 0.0f;

    const uint32_t mb = sbase + OFF_MB * 4;     // hbar0, hbar1, ybar0, ybar1
    if (tid == 0) {
        mbar_init(mb + 0, 8);  mbar_init(mb + 8, 8);
        mbar_init(mb + 16, 8); mbar_init(mb + 24, 8);
    }
    __syncthreads();
    cluster_sync_all();

    uint32_t peer[8];
    #pragma unroll
    for (int j = 0; j < 8; j++) peer[j] = mapa32(mb, (uint32_t)j);

    uint32_t hph0 = 0, hph1 = 0, yph0 = 0, yph1 = 0;

    const float* whR = whh_s + (0 * UNITS + unit) * WHS + q * 64;
    const float* whZ = whh_s + (1 * UNITS + unit) * WHS + q * 64;
    const float* whN = whh_s + (2 * UNITS + unit) * WHS + q * 64;
    const float* wxR = wih_s + (0 * UNITS + unit) * WIS + q * 32;
    const float* wxZ = wih_s + (1 * UNITS + unit) * WIS + q * 32;
    const float* wxN = wih_s + (2 * UNITS + unit) * WIS + q * 32;
    const float* wyR = wih_s + (0 * UNITS + unit) * WIS + INSZ + q * 16;
    const float* wyZ = wih_s + (1 * UNITS + unit) * WIS + INSZ + q * 16;
    const float* wyN = wih_s + (2 * UNITS + unit) * WIS + INSZ + q * 16;

    float4 xreg;
    if (tid < 256) {
        int row = tid >> 5, c = tid & 31;
        xreg = reinterpret_cast<const float4*>(x)[((size_t)(b0 + row) * TSTEPS) * 32 + c];
    }

    for (int t = 0; t < TSTEPS; t++) {
        const int cur = t & 1, nxt = cur ^ 1;

        // x_t store + x_{t+1} prefetch
        if (tid < 256) {
            int row = tid >> 5, c = tid & 31;
            *reinterpret_cast<float4*>(x_s + row * XS + c * 4) = xreg;
            if (t + 1 < TSTEPS)
                xreg = reinterpret_cast<const float4*>(x)
                           [((size_t)(b0 + row) * TSTEPS + t + 1) * 32 + c];
        }

        if (t > 0) {
            // wait h_t, stage h_t
            uint32_t ph = cur ? hph1 : hph0;
            wait_parity(mb + (uint32_t)cur * 8, ph);
            if (cur) hph1 ^= 1; else hph0 ^= 1;
            {
                int row = tid >> 6, c = tid & 63;
                float4 v = reinterpret_cast<const float4*>(g_h[cur])[(b0 + row) * 64 + c];
                *reinterpret_cast<float4*>(h_s + row * HS + c * 4) = v;
            }
        }
        __syncthreads();                                       // S2

        // ---- y_t by 128 threads (pair, K-half = 128 floats); others go to gh ----
        if (t > 0 && tid < 128) {
            const int pair = tid & 63, kh = tid >> 6;
            const int yb = pair & 7, ol = pair >> 3;
            const ulonglong2* hp =
                reinterpret_cast<const ulonglong2*>(h_s + yb * HS + kh * 128);
            const ulonglong2* fp =
                reinterpret_cast<const ulonglong2*>(fc_s + ol * FCS + kh * 128);
            ull a0 = 0, a1 = 0;
            #pragma unroll 8
            for (int c = 0; c < 32; c++) {              // 32 u2 = 128 floats
                ulonglong2 hv = hp[c], fv = fp[c];
                a0 = ffma2(hv.x, fv.x, a0);
                a1 = ffma2(hv.y, fv.y, a1);
            }
            float part = sumf2(a0) + sumf2(a1);
            if (kh) ysum_s[pair] = part;
            barn(3, 128);
            if (!kh) {
                float yv = tanhf(part + ysum_s[pair] + fcb_s[ol]);
                g_y[cur][(b0 + yb) * OUTSZ + slice * 8 + ol] = yv;
                barn(1, 64);
                if (tid < 8) mbar_arrive_remote(peer[tid] + 16 + (uint32_t)cur * 8);
            }
        }

        ull aR0 = 0, aR1 = 0, aZ0 = 0, aZ1 = 0;
        ull aNi0 = 0, aNi1 = 0, aNh0 = 0, aNh1 = 0;

        // ---- gh (quarter of K=256 -> 64 floats, 2 rows) ----
        {
            const ulonglong2* h0 = reinterpret_cast<const ulonglong2*>(h_s + b * HS + q * 64);
            const ulonglong2* h1 = reinterpret_cast<const ulonglong2*>(h_s + (b + 4) * HS + q * 64);
            const ulonglong2* r0 = reinterpret_cast<const ulonglong2*>(whR);
            const ulonglong2* r1 = reinterpret_cast<const ulonglong2*>(whZ);
            const ulonglong2* r2 = reinterpret_cast<const ulonglong2*>(whN);
            #pragma unroll 8
            for (int c = 0; c < 16; c++) {
                ulonglong2 v0 = r0[c], hv0 = h0[c], hv1 = h1[c];
                aR0 = ffma2(hv0.x, v0.x, aR0); aR0 = ffma2(hv0.y, v0.y, aR0);
                aR1 = ffma2(hv1.x, v0.x, aR1); aR1 = ffma2(hv1.y, v0.y, aR1);
                ulonglong2 v1 = r1[c];
                aZ0 = ffma2(hv0.x, v1.x, aZ0); aZ0 = ffma2(hv0.y, v1.y, aZ0);
                aZ1 = ffma2(hv1.x, v1.x, aZ1); aZ1 = ffma2(hv1.y, v1.y, aZ1);
                ulonglong2 v2 = r2[c];
                aNh0 = ffma2(hv0.x, v2.x, aNh0); aNh0 = ffma2(hv0.y, v2.y, aNh0);
                aNh1 = ffma2(hv1.x, v2.x, aNh1); aNh1 = ffma2(hv1.y, v2.y, aNh1);
            }
        }
        // ---- gi_x (quarter of I=128 -> 32 floats, 2 rows) ----
        {
            const ulonglong2* x0 = reinterpret_cast<const ulonglong2*>(x_s + b * XS + q * 32);
            const ulonglong2* x1 = reinterpret_cast<const ulonglong2*>(x_s + (b + 4) * XS + q * 32);
            const ulonglong2* r0 = reinterpret_cast<const ulonglong2*>(wxR);
            const ulonglong2* r1 = reinterpret_cast<const ulonglong2*>(wxZ);
            const ulonglong2* r2 = reinterpret_cast<const ulonglong2*>(wxN);
            #pragma unroll 8
            for (int c = 0; c < 8; c++) {
                ulonglong2 v0 = r0[c], xv0 = x0[c], xv1 = x1[c];
                aR0 = ffma2(xv0.x, v0.x, aR0); aR0 = ffma2(xv0.y, v0.y, aR0);
                aR1 = ffma2(xv1.x, v0.x, aR1); aR1 = ffma2(xv1.y, v0.y, aR1);
                ulonglong2 v1 = r1[c];
                aZ0 = ffma2(xv0.x, v1.x, aZ0); aZ0 = ffma2(xv0.y, v1.y, aZ0);
                aZ1 = ffma2(xv1.x, v1.x, aZ1); aZ1 = ffma2(xv1.y, v1.y, aZ1);
                ulonglong2 v2 = r2[c];
                aNi0 = ffma2(xv0.x, v2.x, aNi0); aNi0 = ffma2(xv0.y, v2.y, aNi0);
                aNi1 = ffma2(xv1.x, v2.x, aNi1); aNi1 = ffma2(xv1.y, v2.y, aNi1);
            }
        }

        // ---- wait + stage y_t ----
        if (t > 0) {
            if (tid < 128) {
                uint32_t ph = cur ? yph1 : yph0;
                wait_parity(mb + 16 + (uint32_t)cur * 8, ph);
                int row = tid >> 4, c = tid & 15;
                float4 v = reinterpret_cast<const float4*>(g_y[cur])[(b0 + row) * 16 + c];
                *reinterpret_cast<float4*>(y_s + row * YS + c * 4) = v;
            }
            if (cur) yph1 ^= 1; else yph0 ^= 1;
            __syncthreads();                                   // S4
        }

        // ---- gi_y (quarter of O=64 -> 16 floats, 2 rows) ----
        {
            const ulonglong2* y0 = reinterpret_cast<const ulonglong2*>(y_s + b * YS + q * 16);
            const ulonglong2* y1 = reinterpret_cast<const ulonglong2*>(y_s + (b + 4) * YS + q * 16);
            const ulonglong2* r0 = reinterpret_cast<const ulonglong2*>(wyR);
            const ulonglong2* r1 = reinterpret_cast<const ulonglong2*>(wyZ);
            const ulonglong2* r2 = reinterpret_cast<const ulonglong2*>(wyN);
            #pragma unroll
            for (int c = 0; c < 4; c++) {
                ulonglong2 v0 = r0[c], yv0 = y0[c], yv1 = y1[c];
                aR0 = ffma2(yv0.x, v0.x, aR0); aR0 = ffma2(yv0.y, v0.y, aR0);
                aR1 = ffma2(yv1.x, v0.x, aR1); aR1 = ffma2(yv1.y, v0.y, aR1);
                ulonglong2 v1 = r1[c];
                aZ0 = ffma2(yv0.x, v1.x, aZ0); aZ0 = ffma2(yv0.y, v1.y, aZ0);
                aZ1 = ffma2(yv1.x, v1.x, aZ1); aZ1 = ffma2(yv1.y, v1.y, aZ1);
                ulonglong2 v2 = r2[c];
                aNi0 = ffma2(yv0.x, v2.x, aNi0); aNi0 = ffma2(yv0.y, v2.y, aNi0);
                aNi1 = ffma2(yv1.x, v2.x, aNi1); aNi1 = ffma2(yv1.y, v2.y, aNi1);
            }
        }

        // ---- combine quarters ----
        if (q != 0) {
            p_s[(q - 1) * 256 + b * 32 + unit] =
                make_float4(sumf2(aR0), sumf2(aZ0), sumf2(aNi0), sumf2(aNh0));
            p_s[(q - 1) * 256 + (b + 4) * 32 + unit] =
                make_float4(sumf2(aR1), sumf2(aZ1), sumf2(aNi1), sumf2(aNh1));
        }
        __syncthreads();                                       // S5

        if (q == 0) {
            float4 s0 = make_float4(sumf2(aR0), sumf2(aZ0), sumf2(aNi0), sumf2(aNh0));
            float4 s1 = make_float4(sumf2(aR1), sumf2(aZ1), sumf2(aNi1), sumf2(aNh1));
            #pragma unroll
            for (int j = 0; j < 3; j++) {
                float4 pa = p_s[j * 256 + b * 32 + unit];
                float4 pb = p_s[j * 256 + (b + 4) * 32 + unit];
                s0.x += pa.x; s0.y += pa.y; s0.z += pa.z; s0.w += pa.w;
                s1.x += pb.x; s1.y += pb.y; s1.z += pb.z; s1.w += pb.w;
            }
            float biR = bih_s[unit] + bhh_s[unit];
            float biZ = bih_s[32 + unit] + bhh_s[32 + unit];
            float biN = bih_s[64 + unit];
            float bhN = bhh_s[64 + unit];

            float r0v = 1.0f / (1.0f + __expf(-(s0.x + biR)));
            float z0v = 1.0f / (1.0f + __expf(-(s0.y + biZ)));
            float n0v = tanhf(s0.z + biN + r0v * (s0.w + bhN));
            float hp0 = h_s[b * HS + slice * UNITS + unit];
            hstg_s[b * HSTG + unit] = (1.0f - z0v) * n0v + z0v * hp0;

            float r1v = 1.0f / (1.0f + __expf(-(s1.x + biR)));
            float z1v = 1.0f / (1.0f + __expf(-(s1.y + biZ)));
            float n1v = tanhf(s1.z + biN + r1v * (s1.w + bhN));
            float hp1 = h_s[(b + 4) * HS + slice * UNITS + unit];
            hstg_s[(b + 4) * HSTG + unit] = (1.0f - z1v) * n1v + z1v * hp1;

            barn(3, 128);
            if (tid < 64) {
                int row = tid >> 3, cg = tid & 7;
                float4 v = *reinterpret_cast<float4*>(hstg_s + row * HSTG + cg * 4);
                reinterpret_cast<float4*>(g_h[nxt])
                    [(b0 + row) * 64 + slice * 8 + cg] = v;
                barn(1, 64);
                if (tid < 8) mbar_arrive_remote(peer[tid] + (uint32_t)nxt * 8);
            }
        }
    }

    // ---- final: wait h_T (bar 0), compute out ----
    wait_parity(mb + 0, hph0);
    {
        int row = tid >> 6, c = tid & 63;
        float4 v = reinterpret_cast<const float4*>(g_h[0])[(b0 + row) * 64 + c];
        *reinterpret_cast<float4*>(h_s + row * HS + c * 4) = v;
    }
    __syncthreads();
    if (tid < 64) {
        const int yb = tid & 7, ol = tid >> 3;
        const ulonglong2* hp = reinterpret_cast<const ulonglong2*>(h_s + yb * HS);
        const ulonglong2* fp = reinterpret_cast<const ulonglong2*>(fc_s + ol * FCS);
        ull a0 = 0, a1 = 0;
        #pragma unroll 8
        for (int c = 0; c < 64; c++) {                  // 64 u2 = 256 floats
            ulonglong2 hv = hp[c], fv = fp[c];
            a0 = ffma2(hv.x, fv.x, a0);
            a1 = ffma2(hv.y, fv.y, a1);
        }
        out[(b0 + yb) * OUTSZ + slice * 8 + ol] =
            tanhf(sumf2(a0) + sumf2(a1) + fcb_s[ol]);
    }
    cluster_sync_all();
}

extern "C" void kernel_launch(void* const* d_in, const int* in_sizes, int n_in,
                              void* d_out, int out_size) {
    (void)in_sizes; (void)n_in; (void)out_size;
    const float* x    = (const float*)d_in[0];
    const float* w_ih = (const float*)d_in[1];
    const float* w_hh = (const float*)d_in[2];
    const float* b_ih = (const float*)d_in[3];
    const float* b_hh = (const float*)d_in[4];
    const float* fc_w = (const float*)d_in[5];
    const float* fc_b = (const float*)d_in[6];
    float* out = (float*)d_out;

    const int smem_bytes = SMEM_FLOATS * (int)sizeof(float); // 212,896 B
    cudaFuncSetAttribute(jordan_kernel,
                         cudaFuncAttributeMaxDynamicSharedMemorySize,
                         smem_bytes);

    jordan_kernel<<<NBLK, NTHR, smem_bytes>>>(x, w_ih, w_hh, b_ih, b_hh,
                                              fc_w, fc_b, out);
}

// round 8
// speedup vs baseline: 1.3950x; 1.3950x over previous
#include <cuda_runtime.h>
#include <cstdint>
#include <cstddef>

// Jordan GRU, B=128, T=2048, I=128, H=256, O=64.
// 16 groups x 8 slices; CTA = 8 batch rows x 32 hidden units, 512 threads.
// Thread = (K-quarter q, unit, batch-pair b/{b,b+4}) -> 2 rows per thread.
// Data via L2 (STG/LDG); signaling via L2 release/acquire poll flags (R5 path).
// Roles: q0 warps -> y feedback; q1 warps -> combine+gates+h writeback.

#define TSTEPS 2048
#define INSZ 128
#define HID 256
#define OUTSZ 64
#define GIN 192
#define NBLK 128
#define NTHR 512
#define ROWS 8
#define UNITS 32
#define NSLICE 8

#define HS 260
#define XS 132
#define YS 68
#define WHS 260
#define WIS 196
#define FCS 264
#define HSTG 36

// float offsets in dynamic smem
#define OFF_H    0
#define OFF_X    (OFF_H + ROWS * HS)         // 2080
#define OFF_Y    (OFF_X + ROWS * XS)         // 3136
#define OFF_P    (OFF_Y + ROWS * YS)         // 3680  (3*256 float4)
#define OFF_YS   (OFF_P + 3 * 256 * 4)       // 6752
#define OFF_HST  (OFF_YS + 64)               // 6816
#define OFF_WHH  (OFF_HST + ROWS * HSTG)     // 7104
#define OFF_WIH  (OFF_WHH + 96 * WHS)        // 32064
#define OFF_FC   (OFF_WIH + 96 * WIS)        // 50880
#define OFF_BIH  (OFF_FC + 8 * FCS)          // 52992
#define OFF_BHH  (OFF_BIH + 96)
#define OFF_FCB  (OFF_BHH + 96)
#define SMEM_FLOATS (OFF_FCB + 16)           // -> ~212.8 KB

typedef unsigned long long ull;

__device__ float g_h[2][128 * HID];
__device__ float g_y[2][128 * OUTSZ];
__device__ unsigned g_hflag[NBLK];
__device__ unsigned g_yflag[NBLK];

__device__ __forceinline__ ull ffma2(ull a, ull b, ull c) {
    ull d; asm("fma.rn.f32x2 %0, %1, %2, %3;" : "=l"(d) : "l"(a), "l"(b), "l"(c));
    return d;
}
__device__ __forceinline__ float sumf2(ull v) {
    float a, b; asm("mov.b64 {%0, %1}, %2;" : "=f"(a), "=f"(b) : "l"(v));
    return a + b;
}
__device__ __forceinline__ unsigned ld_acq(const unsigned* p) {
    unsigned v; asm volatile("ld.acquire.gpu.global.u32 %0, [%1];" : "=r"(v) : "l"(p));
    return v;
}
__device__ __forceinline__ void st_rel(unsigned* p, unsigned v) {
    asm volatile("st.release.gpu.global.u32 [%0], %1;" :: "l"(p), "r"(v));
}
__device__ __forceinline__ void barn(int id, int cnt) {
    asm volatile("bar.sync %0, %1;" :: "r"(id), "r"(cnt) : "memory");
}

__global__ void jordan_init_kernel() {
    int i = blockIdx.x * blockDim.x + threadIdx.x;
    if (i < NBLK) { g_hflag[i] = 0u; g_yflag[i] = 0u; }
}

__global__ void __launch_bounds__(NTHR, 1) jordan_kernel(
    const float* __restrict__ x,      // [B, T, I]
    const float* __restrict__ w_ih,   // [3H, GIN]
    const float* __restrict__ w_hh,   // [3H, H]
    const float* __restrict__ b_ih,   // [3H]
    const float* __restrict__ b_hh,   // [3H]
    const float* __restrict__ fc_w,   // [O, H]
    const float* __restrict__ fc_b,   // [O]
    float* __restrict__ out)          // [B, O]
{
    extern __shared__ float sm[];
    float*  h_s    = sm + OFF_H;
    float*  x_s    = sm + OFF_X;
    float*  y_s    = sm + OFF_Y;
    float4* p_s    = reinterpret_cast<float4*>(sm + OFF_P);
    float*  ysum_s = sm + OFF_YS;
    float*  hstg_s = sm + OFF_HST;
    float*  whh_s  = sm + OFF_WHH;
    float*  wih_s  = sm + OFF_WIH;
    float*  fc_s   = sm + OFF_FC;
    float*  bih_s  = sm + OFF_BIH;
    float*  bhh_s  = sm + OFF_BHH;
    float*  fcb_s  = sm + OFF_FCB;

    const int tid  = threadIdx.x;
    const int q    = tid >> 7;          // K-quarter 0..3
    const int wg   = tid & 127;
    const int unit = wg >> 2;           // 0..31
    const int b    = wg & 3;            // rows b and b+4

    const int blk   = blockIdx.x;
    const int group = blk >> 3;
    const int slice = blk & 7;
    const int b0    = group * ROWS;
    const int fbase = group * NSLICE;

    // ---- weights / biases / state init ----
    for (int i = tid; i < 96 * HID; i += NTHR) {
        int row = i >> 8, k = i & 255;
        whh_s[row * WHS + k] =
            w_hh[((row >> 5) * HID + slice * UNITS + (row & 31)) * HID + k];
    }
    for (int i = tid; i < 96 * GIN; i += NTHR) {
        int row = i / GIN, k = i - row * GIN;
        wih_s[row * WIS + k] =
            w_ih[((row >> 5) * HID + slice * UNITS + (row & 31)) * GIN + k];
    }
    for (int i = tid; i < 8 * HID; i += NTHR) {
        int r = i >> 8, k = i & 255;
        fc_s[r * FCS + k] = fc_w[(slice * 8 + r) * HID + k];
    }
    if (tid < 96) {
        int grow = (tid >> 5) * HID + slice * UNITS + (tid & 31);
        bih_s[tid] = b_ih[grow];
        bhh_s[tid] = b_hh[grow];
    }
    if (tid < 8) fcb_s[tid] = fc_b[slice * 8 + tid];
    for (int i = tid; i < ROWS * HS; i += NTHR) h_s[i] = 0.0f;
    for (int i = tid; i < ROWS * YS; i += NTHR) y_s[i] = 0.0f;
    __syncthreads();

    const float* whR = whh_s + (0 * UNITS + unit) * WHS + q * 64;
    const float* whZ = whh_s + (1 * UNITS + unit) * WHS + q * 64;
    const float* whN = whh_s + (2 * UNITS + unit) * WHS + q * 64;
    const float* wxR = wih_s + (0 * UNITS + unit) * WIS + q * 32;
    const float* wxZ = wih_s + (1 * UNITS + unit) * WIS + q * 32;
    const float* wxN = wih_s + (2 * UNITS + unit) * WIS + q * 32;
    const float* wyR = wih_s + (0 * UNITS + unit) * WIS + INSZ + q * 16;
    const float* wyZ = wih_s + (1 * UNITS + unit) * WIS + INSZ + q * 16;
    const float* wyN = wih_s + (2 * UNITS + unit) * WIS + INSZ + q * 16;

    float4 xreg;
    if (tid < 256) {
        int row = tid >> 5, c = tid & 31;
        xreg = reinterpret_cast<const float4*>(x)[((size_t)(b0 + row) * TSTEPS) * 32 + c];
    }

    for (int t = 0; t < TSTEPS; t++) {
        const int cur = t & 1, nxt = cur ^ 1;

        // x_t store + x_{t+1} prefetch
        if (tid < 256) {
            int row = tid >> 5, c = tid & 31;
            *reinterpret_cast<float4*>(x_s + row * XS + c * 4) = xreg;
            if (t + 1 < TSTEPS)
                xreg = reinterpret_cast<const float4*>(x)
                           [((size_t)(b0 + row) * TSTEPS + t + 1) * 32 + c];
        }

        // wait for h_t (8 poll threads), stage h_t (one float4 per thread)
        if (t > 0) {
            if (tid < NSLICE) { while ((int)ld_acq(&g_hflag[fbase + tid]) < t) { } }
        }
        __syncthreads();                                       // S1
        if (t > 0) {
            int row = tid >> 6, c = tid & 63;
            float4 v = reinterpret_cast<const float4*>(g_h[cur])[(b0 + row) * 64 + c];
            *reinterpret_cast<float4*>(h_s + row * HS + c * 4) = v;
        }
        __syncthreads();                                       // S2

        // ---- y_t by q0 warps (tid<128): pair x K-half (128 floats each) ----
        if (t > 0 && tid < 128) {
            const int pair = tid & 63, kh = tid >> 6;
            const int yb = pair & 7, ol = pair >> 3;
            const ulonglong2* hp =
                reinterpret_cast<const ulonglong2*>(h_s + yb * HS + kh * 128);
            const ulonglong2* fp =
                reinterpret_cast<const ulonglong2*>(fc_s + ol * FCS + kh * 128);
            ull a0 = 0, a1 = 0;
            #pragma unroll 8
            for (int c = 0; c < 32; c++) {
                ulonglong2 hv = hp[c], fv = fp[c];
                a0 = ffma2(hv.x, fv.x, a0);
                a1 = ffma2(hv.y, fv.y, a1);
            }
            float part = sumf2(a0) + sumf2(a1);
            if (kh) ysum_s[pair] = part;
            barn(3, 128);
            if (!kh) {
                float yv = tanhf(part + ysum_s[pair] + fcb_s[ol]);
                g_y[cur][(b0 + yb) * OUTSZ + slice * 8 + ol] = yv;
                __threadfence();
                barn(1, 64);
                if (tid == 0) st_rel(&g_yflag[blk], (unsigned)t);
            }
        }

        ull aR0 = 0, aR1 = 0, aZ0 = 0, aZ1 = 0;
        ull aNi0 = 0, aNi1 = 0, aNh0 = 0, aNh1 = 0;

        // ---- gh (quarter of K=256 -> 64 floats, 2 rows) ----
        {
            const ulonglong2* h0 = reinterpret_cast<const ulonglong2*>(h_s + b * HS + q * 64);
            const ulonglong2* h1 = reinterpret_cast<const ulonglong2*>(h_s + (b + 4) * HS + q * 64);
            const ulonglong2* r0 = reinterpret_cast<const ulonglong2*>(whR);
            const ulonglong2* r1 = reinterpret_cast<const ulonglong2*>(whZ);
            const ulonglong2* r2 = reinterpret_cast<const ulonglong2*>(whN);
            #pragma unroll 8
            for (int c = 0; c < 16; c++) {
                ulonglong2 v0 = r0[c], hv0 = h0[c], hv1 = h1[c];
                aR0 = ffma2(hv0.x, v0.x, aR0); aR0 = ffma2(hv0.y, v0.y, aR0);
                aR1 = ffma2(hv1.x, v0.x, aR1); aR1 = ffma2(hv1.y, v0.y, aR1);
                ulonglong2 v1 = r1[c];
                aZ0 = ffma2(hv0.x, v1.x, aZ0); aZ0 = ffma2(hv0.y, v1.y, aZ0);
                aZ1 = ffma2(hv1.x, v1.x, aZ1); aZ1 = ffma2(hv1.y, v1.y, aZ1);
                ulonglong2 v2 = r2[c];
                aNh0 = ffma2(hv0.x, v2.x, aNh0); aNh0 = ffma2(hv0.y, v2.y, aNh0);
                aNh1 = ffma2(hv1.x, v2.x, aNh1); aNh1 = ffma2(hv1.y, v2.y, aNh1);
            }
        }
        // ---- gi_x (quarter of I=128 -> 32 floats, 2 rows) ----
        {
            const ulonglong2* x0 = reinterpret_cast<const ulonglong2*>(x_s + b * XS + q * 32);
            const ulonglong2* x1 = reinterpret_cast<const ulonglong2*>(x_s + (b + 4) * XS + q * 32);
            const ulonglong2* r0 = reinterpret_cast<const ulonglong2*>(wxR);
            const ulonglong2* r1 = reinterpret_cast<const ulonglong2*>(wxZ);
            const ulonglong2* r2 = reinterpret_cast<const ulonglong2*>(wxN);
            #pragma unroll 8
            for (int c = 0; c < 8; c++) {
                ulonglong2 v0 = r0[c], xv0 = x0[c], xv1 = x1[c];
                aR0 = ffma2(xv0.x, v0.x, aR0); aR0 = ffma2(xv0.y, v0.y, aR0);
                aR1 = ffma2(xv1.x, v0.x, aR1); aR1 = ffma2(xv1.y, v0.y, aR1);
                ulonglong2 v1 = r1[c];
                aZ0 = ffma2(xv0.x, v1.x, aZ0); aZ0 = ffma2(xv0.y, v1.y, aZ0);
                aZ1 = ffma2(xv1.x, v1.x, aZ1); aZ1 = ffma2(xv1.y, v1.y, aZ1);
                ulonglong2 v2 = r2[c];
                aNi0 = ffma2(xv0.x, v2.x, aNi0); aNi0 = ffma2(xv0.y, v2.y, aNi0);
                aNi1 = ffma2(xv1.x, v2.x, aNi1); aNi1 = ffma2(xv1.y, v2.y, aNi1);
            }
        }

        // ---- wait + stage y_t ----
        if (t > 0) {
            if (tid < NSLICE) { while ((int)ld_acq(&g_yflag[fbase + tid]) < t) { } }
            __syncthreads();                                   // S3
            if (tid < 128) {
                int row = tid >> 4, c = tid & 15;
                float4 v = reinterpret_cast<const float4*>(g_y[cur])[(b0 + row) * 16 + c];
                *reinterpret_cast<float4*>(y_s + row * YS + c * 4) = v;
            }
            __syncthreads();                                   // S4
        }

        // ---- gi_y (quarter of O=64 -> 16 floats, 2 rows) ----
        {
            const ulonglong2* y0 = reinterpret_cast<const ulonglong2*>(y_s + b * YS + q * 16);
            const ulonglong2* y1 = reinterpret_cast<const ulonglong2*>(y_s + (b + 4) * YS + q * 16);
            const ulonglong2* r0 = reinterpret_cast<const ulonglong2*>(wyR);
            const ulonglong2* r1 = reinterpret_cast<const ulonglong2*>(wyZ);
            const ulonglong2* r2 = reinterpret_cast<const ulonglong2*>(wyN);
            #pragma unroll
            for (int c = 0; c < 4; c++) {
                ulonglong2 v0 = r0[c], yv0 = y0[c], yv1 = y1[c];
                aR0 = ffma2(yv0.x, v0.x, aR0); aR0 = ffma2(yv0.y, v0.y, aR0);
                aR1 = ffma2(yv1.x, v0.x, aR1); aR1 = ffma2(yv1.y, v0.y, aR1);
                ulonglong2 v1 = r1[c];
                aZ0 = ffma2(yv0.x, v1.x, aZ0); aZ0 = ffma2(yv0.y, v1.y, aZ0);
                aZ1 = ffma2(yv1.x, v1.x, aZ1); aZ1 = ffma2(yv1.y, v1.y, aZ1);
                ulonglong2 v2 = r2[c];
                aNi0 = ffma2(yv0.x, v2.x, aNi0); aNi0 = ffma2(yv0.y, v2.y, aNi0);
                aNi1 = ffma2(yv1.x, v2.x, aNi1); aNi1 = ffma2(yv1.y, v2.y, aNi1);
            }
        }

        // ---- partial store (q0, q2, q3); q1 combines ----
        if (q != 1) {
            int slot = (q == 0) ? 0 : (q - 1);                 // 0,1,2
            p_s[slot * 256 + b * 32 + unit] =
                make_float4(sumf2(aR0), sumf2(aZ0), sumf2(aNi0), sumf2(aNh0));
            p_s[slot * 256 + (b + 4) * 32 + unit] =
                make_float4(sumf2(aR1), sumf2(aZ1), sumf2(aNi1), sumf2(aNh1));
        }
        __syncthreads();                                       // S5

        if (q == 1) {
            float4 s0 = make_float4(sumf2(aR0), sumf2(aZ0), sumf2(aNi0), sumf2(aNh0));
            float4 s1 = make_float4(sumf2(aR1), sumf2(aZ1), sumf2(aNi1), sumf2(aNh1));
            #pragma unroll
            for (int j = 0; j < 3; j++) {
                float4 pa = p_s[j * 256 + b * 32 + unit];
                float4 pb = p_s[j * 256 + (b + 4) * 32 + unit];
                s0.x += pa.x; s0.y += pa.y; s0.z += pa.z; s0.w += pa.w;
                s1.x += pb.x; s1.y += pb.y; s1.z += pb.z; s1.w += pb.w;
            }
            float biR = bih_s[unit] + bhh_s[unit];
            float biZ = bih_s[32 + unit] + bhh_s[32 + unit];
            float biN = bih_s[64 + unit];
            float bhN = bhh_s[64 + unit];

            float r0v = 1.0f / (1.0f + __expf(-(s0.x + biR)));
            float z0v = 1.0f / (1.0f + __expf(-(s0.y + biZ)));
            float n0v = tanhf(s0.z + biN + r0v * (s0.w + bhN));
            float hp0 = h_s[b * HS + slice * UNITS + unit];
            hstg_s[b * HSTG + unit] = (1.0f - z0v) * n0v + z0v * hp0;

            float r1v = 1.0f / (1.0f + __expf(-(s1.x + biR)));
            float z1v = 1.0f / (1.0f + __expf(-(s1.y + biZ)));
            float n1v = tanhf(s1.z + biN + r1v * (s1.w + bhN));
            float hp1 = h_s[(b + 4) * HS + slice * UNITS + unit];
            hstg_s[(b + 4) * HSTG + unit] = (1.0f - z1v) * n1v + z1v * hp1;

            barn(4, 128);                                       // q1 warps only
            if (tid < 192) {                                    // tid 128..191
                int l = tid - 128;
                int row = l >> 3, cg = l & 7;
                float4 v = *reinterpret_cast<float4*>(hstg_s + row * HSTG + cg * 4);
                reinterpret_cast<float4*>(g_h[nxt])
                    [(b0 + row) * 64 + slice * 8 + cg] = v;
                __threadfence();
                barn(5, 64);
                if (tid == 128) st_rel(&g_hflag[blk], (unsigned)(t + 1));
            }
        }
    }

    // ---- final: wait h_T, compute out ----
    if (tid < NSLICE) { while ((int)ld_acq(&g_hflag[fbase + tid]) < TSTEPS) { } }
    __syncthreads();
    {
        int row = tid >> 6, c = tid & 63;
        float4 v = reinterpret_cast<const float4*>(g_h[0])[(b0 + row) * 64 + c];
        *reinterpret_cast<float4*>(h_s + row * HS + c * 4) = v;
    }
    __syncthreads();
    if (tid < 64) {
        const int yb = tid & 7, ol = tid >> 3;
        const ulonglong2* hp = reinterpret_cast<const ulonglong2*>(h_s + yb * HS);
        const ulonglong2* fp = reinterpret_cast<const ulonglong2*>(fc_s + ol * FCS);
        ull a0 = 0, a1 = 0;
        #pragma unroll 8
        for (int c = 0; c < 64; c++) {
            ulonglong2 hv = hp[c], fv = fp[c];
            a0 = ffma2(hv.x, fv.x, a0);
            a1 = ffma2(hv.y, fv.y, a1);
        }
        out[(b0 + yb) * OUTSZ + slice * 8 + ol] =
            tanhf(sumf2(a0) + sumf2(a1) + fcb_s[ol]);
    }
}

extern "C" void kernel_launch(void* const* d_in, const int* in_sizes, int n_in,
                              void* d_out, int out_size) {
    (void)in_sizes; (void)n_in; (void)out_size;
    const float* x    = (const float*)d_in[0];
    const float* w_ih = (const float*)d_in[1];
    const float* w_hh = (const float*)d_in[2];
    const float* b_ih = (const float*)d_in[3];
    const float* b_hh = (const float*)d_in[4];
    const float* fc_w = (const float*)d_in[5];
    const float* fc_b = (const float*)d_in[6];
    float* out = (float*)d_out;

    const int smem_bytes = SMEM_FLOATS * (int)sizeof(float);
    cudaFuncSetAttribute(jordan_kernel,
                         cudaFuncAttributeMaxDynamicSharedMemorySize,
                         smem_bytes);

    jordan_init_kernel<<<1, NBLK>>>();
    jordan_kernel<<<NBLK, NTHR, smem_bytes>>>(x, w_ih, w_hh, b_ih, b_hh,
                                              fc_w, fc_b, out);
}

// round 9
// speedup vs baseline: 1.6668x; 1.1949x over previous
#include <cuda_runtime.h>
#include <cstdint>
#include <cstddef>

// Jordan GRU, B=128, T=2048, I=128, H=256, O=64.
// 16 groups x 8 slices; CTA = 8 batch rows x 32 hidden units, 512 threads.
// Thread = (K-quarter q, unit, batch-pair) -> 2 rows per thread.
// SINGLE exchange per step: producers publish hnew + fc-partials (ypart)
// under one release flag; consumers reduce partials locally -> y_t.

#define TSTEPS 2048
#define INSZ 128
#define HID 256
#define OUTSZ 64
#define GIN 192
#define NBLK 128
#define NTHR 512
#define ROWS 8
#define UNITS 32
#define NSLICE 8

#define HS 260
#define XS 132
#define YS 68
#define WHS 260
#define WIS 196
#define FST 36        // fc-slice row stride (64 rows x 32 k, padded)
#define HSTG 36

// float offsets in dynamic smem
#define OFF_H    0                            // 8*260   = 2080
#define OFF_X    2080                         // 8*132   = 1056
#define OFF_Y    3136                         // 8*68    = 544
#define OFF_P    3680                         // 3*256 float4 = 3072
#define OFF_HST  6752                         // 8*36    = 288
#define OFF_WHH  7040                         // 96*260  = 24960
#define OFF_WIH  32000                        // 96*196  = 18816
#define OFF_FC2  50816                        // 64*36   = 2304
#define OFF_BIH  53120                        // 96
#define OFF_BHH  53216                        // 96
#define OFF_FCB  53312                        // 64
#define SMEM_FLOATS 53392                     // 213,568 B

typedef unsigned long long ull;

__device__ float g_h[2][128 * HID];           // [buf][b][k]
__device__ float g_yp[2][128 * 512];          // [buf][b][slice][o]
__device__ unsigned g_hflag[NBLK];

__device__ __forceinline__ ull ffma2(ull a, ull b, ull c) {
    ull d; asm("fma.rn.f32x2 %0, %1, %2, %3;" : "=l"(d) : "l"(a), "l"(b), "l"(c));
    return d;
}
__device__ __forceinline__ float sumf2(ull v) {
    float a, b; asm("mov.b64 {%0, %1}, %2;" : "=f"(a), "=f"(b) : "l"(v));
    return a + b;
}
__device__ __forceinline__ unsigned ld_acq(const unsigned* p) {
    unsigned v; asm volatile("ld.acquire.gpu.global.u32 %0, [%1];" : "=r"(v) : "l"(p));
    return v;
}
__device__ __forceinline__ void st_rel(unsigned* p, unsigned v) {
    asm volatile("st.release.gpu.global.u32 [%0], %1;" :: "l"(p), "r"(v));
}

__global__ void jordan_init_kernel() {
    int i = blockIdx.x * blockDim.x + threadIdx.x;
    if (i < NBLK) g_hflag[i] = 0u;
}

__global__ void __launch_bounds__(NTHR, 1) jordan_kernel(
    const float* __restrict__ x,      // [B, T, I]
    const float* __restrict__ w_ih,   // [3H, GIN]
    const float* __restrict__ w_hh,   // [3H, H]
    const float* __restrict__ b_ih,   // [3H]
    const float* __restrict__ b_hh,   // [3H]
    const float* __restrict__ fc_w,   // [O, H]
    const float* __restrict__ fc_b,   // [O]
    float* __restrict__ out)          // [B, O]
{
    extern __shared__ float sm[];
    float*  h_s    = sm + OFF_H;
    float*  x_s    = sm + OFF_X;
    float*  y_s    = sm + OFF_Y;
    float4* p_s    = reinterpret_cast<float4*>(sm + OFF_P);
    float*  hstg_s = sm + OFF_HST;
    float*  whh_s  = sm + OFF_WHH;
    float*  wih_s  = sm + OFF_WIH;
    float*  fc2_s  = sm + OFF_FC2;
    float*  bih_s  = sm + OFF_BIH;
    float*  bhh_s  = sm + OFF_BHH;
    float*  fcb_s  = sm + OFF_FCB;

    const int tid  = threadIdx.x;
    const int q    = tid >> 7;          // K-quarter 0..3
    const int wg   = tid & 127;
    const int unit = wg >> 2;           // 0..31
    const int b    = wg & 3;            // rows b and b+4

    const int blk   = blockIdx.x;
    const int group = blk >> 3;
    const int slice = blk & 7;
    const int b0    = group * ROWS;
    const int fbase = group * NSLICE;

    // y-partial worker assignment: 128 threads, (o, row-half)
    int yo = -1, rb = 0;
    if (tid >= 64 && tid < 128)        { yo = tid - 64;  rb = 0; }
    else if (tid >= 320 && tid < 384)  { yo = tid - 320; rb = 4; }

    // ---- load weights / biases, zero state ----
    for (int i = tid; i < 96 * HID; i += NTHR) {
        int row = i >> 8, k = i & 255;
        whh_s[row * WHS + k] =
            w_hh[((row >> 5) * HID + slice * UNITS + (row & 31)) * HID + k];
    }
    for (int i = tid; i < 96 * GIN; i += NTHR) {
        int row = i / GIN, k = i - row * GIN;
        wih_s[row * WIS + k] =
            w_ih[((row >> 5) * HID + slice * UNITS + (row & 31)) * GIN + k];
    }
    for (int i = tid; i < OUTSZ * 32; i += NTHR) {       // own fc k-slice
        int o = i >> 5, k = i & 31;
        fc2_s[o * FST + k] = fc_w[o * HID + slice * 32 + k];
    }
    if (tid < 96) {
        int grow = (tid >> 5) * HID + slice * UNITS + (tid & 31);
        bih_s[tid] = b_ih[grow];
        bhh_s[tid] = b_hh[grow];
    }
    if (tid < 64) fcb_s[tid] = fc_b[tid];
    for (int i = tid; i < ROWS * HS; i += NTHR) h_s[i] = 0.0f;
    for (int i = tid; i < ROWS * YS; i += NTHR) y_s[i] = 0.0f;
    __syncthreads();

    const float* whR = whh_s + (0 * UNITS + unit) * WHS + q * 64;
    const float* whZ = whh_s + (1 * UNITS + unit) * WHS + q * 64;
    const float* whN = whh_s + (2 * UNITS + unit) * WHS + q * 64;
    const float* wxR = wih_s + (0 * UNITS + unit) * WIS + q * 32;
    const float* wxZ = wih_s + (1 * UNITS + unit) * WIS + q * 32;
    const float* wxN = wih_s + (2 * UNITS + unit) * WIS + q * 32;
    const float* wyR = wih_s + (0 * UNITS + unit) * WIS + INSZ + q * 16;
    const float* wyZ = wih_s + (1 * UNITS + unit) * WIS + INSZ + q * 16;
    const float* wyN = wih_s + (2 * UNITS + unit) * WIS + INSZ + q * 16;

    const int srow = tid >> 6;           // staging row 0..7
    const int scol = tid & 63;           // staging col

    float4 xreg;
    if (tid < 256) {
        int row = tid >> 5, c = tid & 31;
        xreg = reinterpret_cast<const float4*>(x)[((size_t)(b0 + row) * TSTEPS) * 32 + c];
    }

    for (int t = 0; t < TSTEPS; t++) {
        const int cur = t & 1, nxt = cur ^ 1;

        // x_t store + x_{t+1} prefetch
        if (tid < 256) {
            int row = tid >> 5, c = tid & 31;
            *reinterpret_cast<float4*>(x_s + row * XS + c * 4) = xreg;
            if (t + 1 < TSTEPS)
                xreg = reinterpret_cast<const float4*>(x)
                           [((size_t)(b0 + row) * TSTEPS + t + 1) * 32 + c];
        }

        if (t > 0) {
            if (tid < NSLICE) { while ((int)ld_acq(&g_hflag[fbase + tid]) < t) { } }
        }
        __syncthreads();                                   // S1
        if (t > 0) {
            // stage h_t (one float4 per thread)
            float4 v = reinterpret_cast<const float4*>(g_h[cur])[(b0 + srow) * 64 + scol];
            *reinterpret_cast<float4*>(h_s + srow * HS + scol * 4) = v;
            // reduce fc partials -> y_t (one (row, o) per thread)
            const float* gp = g_yp[cur] + (b0 + srow) * 512 + scol;
            float s = fcb_s[scol];
            #pragma unroll
            for (int si = 0; si < 8; si++) s += gp[si * 64];
            y_s[srow * YS + scol] = tanhf(s);
        }
        __syncthreads();                                   // S2

        ull aR0 = 0, aR1 = 0, aZ0 = 0, aZ1 = 0;
        ull aNi0 = 0, aNi1 = 0, aNh0 = 0, aNh1 = 0;

        // ---- gh (quarter of K=256 -> 64 floats, 2 rows) ----
        {
            const ulonglong2* h0 = reinterpret_cast<const ulonglong2*>(h_s + b * HS + q * 64);
            const ulonglong2* h1 = reinterpret_cast<const ulonglong2*>(h_s + (b + 4) * HS + q * 64);
            const ulonglong2* r0 = reinterpret_cast<const ulonglong2*>(whR);
            const ulonglong2* r1 = reinterpret_cast<const ulonglong2*>(whZ);
            const ulonglong2* r2 = reinterpret_cast<const ulonglong2*>(whN);
            #pragma unroll 8
            for (int c = 0; c < 16; c++) {
                ulonglong2 v0 = r0[c], hv0 = h0[c], hv1 = h1[c];
                aR0 = ffma2(hv0.x, v0.x, aR0); aR0 = ffma2(hv0.y, v0.y, aR0);
                aR1 = ffma2(hv1.x, v0.x, aR1); aR1 = ffma2(hv1.y, v0.y, aR1);
                ulonglong2 v1 = r1[c];
                aZ0 = ffma2(hv0.x, v1.x, aZ0); aZ0 = ffma2(hv0.y, v1.y, aZ0);
                aZ1 = ffma2(hv1.x, v1.x, aZ1); aZ1 = ffma2(hv1.y, v1.y, aZ1);
                ulonglong2 v2 = r2[c];
                aNh0 = ffma2(hv0.x, v2.x, aNh0); aNh0 = ffma2(hv0.y, v2.y, aNh0);
                aNh1 = ffma2(hv1.x, v2.x, aNh1); aNh1 = ffma2(hv1.y, v2.y, aNh1);
            }
        }
        // ---- gi_x (quarter of I=128 -> 32 floats, 2 rows) ----
        {
            const ulonglong2* x0 = reinterpret_cast<const ulonglong2*>(x_s + b * XS + q * 32);
            const ulonglong2* x1 = reinterpret_cast<const ulonglong2*>(x_s + (b + 4) * XS + q * 32);
            const ulonglong2* r0 = reinterpret_cast<const ulonglong2*>(wxR);
            const ulonglong2* r1 = reinterpret_cast<const ulonglong2*>(wxZ);
            const ulonglong2* r2 = reinterpret_cast<const ulonglong2*>(wxN);
            #pragma unroll 8
            for (int c = 0; c < 8; c++) {
                ulonglong2 v0 = r0[c], xv0 = x0[c], xv1 = x1[c];
                aR0 = ffma2(xv0.x, v0.x, aR0); aR0 = ffma2(xv0.y, v0.y, aR0);
                aR1 = ffma2(xv1.x, v0.x, aR1); aR1 = ffma2(xv1.y, v0.y, aR1);
                ulonglong2 v1 = r1[c];
                aZ0 = ffma2(xv0.x, v1.x, aZ0); aZ0 = ffma2(xv0.y, v1.y, aZ0);
                aZ1 = ffma2(xv1.x, v1.x, aZ1); aZ1 = ffma2(xv1.y, v1.y, aZ1);
                ulonglong2 v2 = r2[c];
                aNi0 = ffma2(xv0.x, v2.x, aNi0); aNi0 = ffma2(xv0.y, v2.y, aNi0);
                aNi1 = ffma2(xv1.x, v2.x, aNi1); aNi1 = ffma2(xv1.y, v2.y, aNi1);
            }
        }
        // ---- gi_y (quarter of O=64 -> 16 floats, 2 rows; y_s ready at S2) ----
        {
            const ulonglong2* y0 = reinterpret_cast<const ulonglong2*>(y_s + b * YS + q * 16);
            const ulonglong2* y1 = reinterpret_cast<const ulonglong2*>(y_s + (b + 4) * YS + q * 16);
            const ulonglong2* r0 = reinterpret_cast<const ulonglong2*>(wyR);
            const ulonglong2* r1 = reinterpret_cast<const ulonglong2*>(wyZ);
            const ulonglong2* r2 = reinterpret_cast<const ulonglong2*>(wyN);
            #pragma unroll
            for (int c = 0; c < 4; c++) {
                ulonglong2 v0 = r0[c], yv0 = y0[c], yv1 = y1[c];
                aR0 = ffma2(yv0.x, v0.x, aR0); aR0 = ffma2(yv0.y, v0.y, aR0);
                aR1 = ffma2(yv1.x, v0.x, aR1); aR1 = ffma2(yv1.y, v0.y, aR1);
                ulonglong2 v1 = r1[c];
                aZ0 = ffma2(yv0.x, v1.x, aZ0); aZ0 = ffma2(yv0.y, v1.y, aZ0);
                aZ1 = ffma2(yv1.x, v1.x, aZ1); aZ1 = ffma2(yv1.y, v1.y, aZ1);
                ulonglong2 v2 = r2[c];
                aNi0 = ffma2(yv0.x, v2.x, aNi0); aNi0 = ffma2(yv0.y, v2.y, aNi0);
                aNi1 = ffma2(yv1.x, v2.x, aNi1); aNi1 = ffma2(yv1.y, v2.y, aNi1);
            }
        }

        // ---- partial store (q0, q2, q3); q1 combines ----
        if (q != 1) {
            int slot = (q == 0) ? 0 : (q - 1);
            p_s[slot * 256 + b * 32 + unit] =
                make_float4(sumf2(aR0), sumf2(aZ0), sumf2(aNi0), sumf2(aNh0));
            p_s[slot * 256 + (b + 4) * 32 + unit] =
                make_float4(sumf2(aR1), sumf2(aZ1), sumf2(aNi1), sumf2(aNh1));
        }
        __syncthreads();                                   // S3

        if (q == 1) {
            float4 s0 = make_float4(sumf2(aR0), sumf2(aZ0), sumf2(aNi0), sumf2(aNh0));
            float4 s1 = make_float4(sumf2(aR1), sumf2(aZ1), sumf2(aNi1), sumf2(aNh1));
            #pragma unroll
            for (int j = 0; j < 3; j++) {
                float4 pa = p_s[j * 256 + b * 32 + unit];
                float4 pb = p_s[j * 256 + (b + 4) * 32 + unit];
                s0.x += pa.x; s0.y += pa.y; s0.z += pa.z; s0.w += pa.w;
                s1.x += pb.x; s1.y += pb.y; s1.z += pb.z; s1.w += pb.w;
            }
            float biR = bih_s[unit] + bhh_s[unit];
            float biZ = bih_s[32 + unit] + bhh_s[32 + unit];
            float biN = bih_s[64 + unit];
            float bhN = bhh_s[64 + unit];

            float r0v = 1.0f / (1.0f + __expf(-(s0.x + biR)));
            float z0v = 1.0f / (1.0f + __expf(-(s0.y + biZ)));
            float n0v = tanhf(s0.z + biN + r0v * (s0.w + bhN));
            float hp0 = h_s[b * HS + slice * UNITS + unit];
            hstg_s[b * HSTG + unit] = (1.0f - z0v) * n0v + z0v * hp0;

            float r1v = 1.0f / (1.0f + __expf(-(s1.x + biR)));
            float z1v = 1.0f / (1.0f + __expf(-(s1.y + biZ)));
            float n1v = tanhf(s1.z + biN + r1v * (s1.w + bhN));
            float hp1 = h_s[(b + 4) * HS + slice * UNITS + unit];
            hstg_s[(b + 4) * HSTG + unit] = (1.0f - z1v) * n1v + z1v * hp1;
        }
        __syncthreads();                                   // S4 (hstg ready)

        // ---- publish hnew (tid<64) + fc partials (128 worker threads) ----
        if (tid < 64) {
            int row = tid >> 3, cg = tid & 7;
            float4 v = *reinterpret_cast<float4*>(hstg_s + row * HSTG + cg * 4);
            reinterpret_cast<float4*>(g_h[nxt])[(b0 + row) * 64 + slice * 8 + cg] = v;
            __threadfence();
        }
        if (yo >= 0) {
            const ulonglong2* fp = reinterpret_cast<const ulonglong2*>(fc2_s + yo * FST);
            ulonglong2 fr[8];
            #pragma unroll
            for (int i = 0; i < 8; i++) fr[i] = fp[i];
            #pragma unroll
            for (int r = 0; r < 4; r++) {
                const ulonglong2* hp =
                    reinterpret_cast<const ulonglong2*>(hstg_s + (rb + r) * HSTG);
                ull a0 = 0, a1 = 0;
                #pragma unroll
                for (int i = 0; i < 8; i++) {
                    ulonglong2 hv = hp[i];
                    a0 = ffma2(hv.x, fr[i].x, a0);
                    a1 = ffma2(hv.y, fr[i].y, a1);
                }
                g_yp[nxt][(b0 + rb + r) * 512 + slice * 64 + yo] = sumf2(a0) + sumf2(a1);
            }
            __threadfence();
        }
        __syncthreads();                                   // S5
        if (tid == 0) st_rel(&g_hflag[blk], (unsigned)(t + 1));
    }

    // ---- final: out = tanh(sum of fc partials of h_T + fcb) ----
    if (tid < NSLICE) { while ((int)ld_acq(&g_hflag[fbase + tid]) < TSTEPS) { } }
    __syncthreads();
    {
        const float* gp = g_yp[0] + (b0 + srow) * 512 + scol;  // T even -> buf 0
        float s = fcb_s[scol];
        #pragma unroll
        for (int si = 0; si < 8; si++) s += gp[si * 64];
        if ((scol >> 3) == slice)
            out[(b0 + srow) * OUTSZ + scol] = tanhf(s);
    }
}

extern "C" void kernel_launch(void* const* d_in, const int* in_sizes, int n_in,
                              void* d_out, int out_size) {
    (void)in_sizes; (void)n_in; (void)out_size;
    const float* x    = (const float*)d_in[0];
    const float* w_ih = (const float*)d_in[1];
    const float* w_hh = (const float*)d_in[2];
    const float* b_ih = (const float*)d_in[3];
    const float* b_hh = (const float*)d_in[4];
    const float* fc_w = (const float*)d_in[5];
    const float* fc_b = (const float*)d_in[6];
    float* out = (float*)d_out;

    const int smem_bytes = SMEM_FLOATS * (int)sizeof(float); // 213,568 B
    cudaFuncSetAttribute(jordan_kernel,
                         cudaFuncAttributeMaxDynamicSharedMemorySize,
                         smem_bytes);

    jordan_init_kernel<<<1, NBLK>>>();
    jordan_kernel<<<NBLK, NTHR, smem_bytes>>>(x, w_ih, w_hh, b_ih, b_hh,
                                              fc_w, fc_b, out);
}